// round 1
// baseline (speedup 1.0000x reference)
#include <cuda_runtime.h>

// Problem constants (fixed by the reference)
#define B_ 32
#define D_ 64
#define T_ 4096
#define K_ 512
#define N_ (B_ * T_)        // 131072 tokens
#define NQ_ (B_ * D_ * T_)  // 8388608 quantized elements

// Scratch (device globals: no allocation allowed)
__device__ int   g_idx[N_];
__device__ float g_cbnorm[K_];
__device__ float g_partial[B_ * D_];   // 2048 per-block loss partials

// ---------------------------------------------------------------------------
// Kernel 0: codebook row norms  ||e_k||^2  (sequential fp32 like the ref sum)
// ---------------------------------------------------------------------------
__global__ void prep_kernel(const float* __restrict__ cb) {
    int k = blockIdx.x * blockDim.x + threadIdx.x;
    if (k < K_) {
        const float* r = cb + k * D_;
        float a = 0.0f;
#pragma unroll
        for (int i = 0; i < D_; ++i) a = fmaf(r[i], r[i], a);
        g_cbnorm[k] = a;
    }
}

// ---------------------------------------------------------------------------
// Kernel 1: argmin over K=512 codes for 256 tokens per block.
// dist_k = fl( fl(||z||^2 + ||e_k||^2) - fl(2 * (z . e_k)) )  -- mimics the
// reference expression (A + B) - 2*C with fp32 rounding at each step.
// Strict '<' keeps the FIRST index on ties (jnp.argmin semantics).
// ---------------------------------------------------------------------------
__global__ __launch_bounds__(256, 1)
void argmin_kernel(const float* __restrict__ z,
                   const float* __restrict__ cb,
                   float* __restrict__ out_idx /* may be null */) {
    extern __shared__ char smraw[];
    float4* cb4 = reinterpret_cast<float4*>(smraw);                 // 512*16 float4 = 128KB
    float*  cn  = reinterpret_cast<float*>(smraw + 131072);         // 512 floats
    float*  zs  = reinterpret_cast<float*>(smraw + 131072 + 2048);  // 64*256 floats = 64KB

    const int tid = threadIdx.x;
    const int b   = blockIdx.x >> 4;          // 16 blocks per batch (4096/256)
    const int t0  = (blockIdx.x & 15) << 8;

    // Load codebook (coalesced, vectorized)
    const float4* cbg = reinterpret_cast<const float4*>(cb);
#pragma unroll 4
    for (int i = tid; i < K_ * 16; i += 256) cb4[i] = cbg[i];
    for (int i = tid; i < K_; i += 256) cn[i] = g_cbnorm[i];

    // Load z tile: zs[d][j] = z[b, d, t0 + j], coalesced over j
#pragma unroll 4
    for (int f = tid; f < D_ * 256; f += 256) {
        int d = f >> 8, j = f & 255;
        zs[f] = z[((b * D_ + d) << 12) + t0 + j];
    }
    __syncthreads();

    // Pull this thread's token into registers
    float zr[D_];
#pragma unroll
    for (int i = 0; i < D_; ++i) zr[i] = zs[i * 256 + tid];

    // ||z||^2 sequentially in fp32
    float A = 0.0f;
#pragma unroll
    for (int i = 0; i < D_; ++i) A = fmaf(zr[i], zr[i], A);

    float bestd = 3.402823466e38f;
    int   bestk = 0;

    for (int k = 0; k < K_; ++k) {
        const float4* cp = cb4 + k * 16;
        float s0 = 0.f, s1 = 0.f, s2 = 0.f, s3 = 0.f;
#pragma unroll
        for (int i = 0; i < 16; ++i) {
            float4 c = cp[i];
            s0 = fmaf(zr[4 * i + 0], c.x, s0);
            s1 = fmaf(zr[4 * i + 1], c.y, s1);
            s2 = fmaf(zr[4 * i + 2], c.z, s2);
            s3 = fmaf(zr[4 * i + 3], c.w, s3);
        }
        float dot  = __fadd_rn(__fadd_rn(s0, s1), __fadd_rn(s2, s3));
        float dist = __fadd_rn(__fadd_rn(A, cn[k]), -__fmul_rn(2.0f, dot));
        if (dist < bestd) { bestd = dist; bestk = k; }
    }

    const int n = b * T_ + t0 + tid;
    g_idx[n] = bestk;
    if (out_idx) out_idx[n] = (float)bestk;
}

// ---------------------------------------------------------------------------
// Kernel 2: gather quantized rows (straight-through arithmetic replicated:
// out = fl(z + fl(q - z))) and deterministic per-block loss partial sums.
// One block per (b, d) row; coalesced over t.
// ---------------------------------------------------------------------------
__global__ __launch_bounds__(256)
void gather_kernel(const float* __restrict__ z,
                   const float* __restrict__ cb,
                   float* __restrict__ out_q /* may be null */) {
    __shared__ float s_col[K_];
    __shared__ float red[256];

    const int tid = threadIdx.x;
    const int blk = blockIdx.x;     // 0 .. B_*D_-1
    const int b   = blk >> 6;
    const int d   = blk & 63;

    for (int i = tid; i < K_; i += 256) s_col[i] = cb[i * D_ + d];
    __syncthreads();

    const long rowoff = (long)(b * D_ + d) * T_;
    float acc = 0.0f;
#pragma unroll
    for (int j = 0; j < 16; ++j) {
        int t = j * 256 + tid;
        int idx = g_idx[b * T_ + t];
        float q  = s_col[idx];
        float zv = z[rowoff + t];
        float diff = __fsub_rn(q, zv);
        if (out_q) out_q[rowoff + t] = __fadd_rn(zv, diff);  // z + (q - z)
        acc = fmaf(diff, diff, acc);
    }

    red[tid] = acc;
    __syncthreads();
    for (int s = 128; s > 0; s >>= 1) {
        if (tid < s) red[tid] += red[tid + s];
        __syncthreads();
    }
    if (tid == 0) g_partial[blk] = red[0];
}

// ---------------------------------------------------------------------------
// Kernel 3: deterministic loss finalize. vq = cl + 0.25*cl, cl = mean((q-z)^2)
// ---------------------------------------------------------------------------
__global__ void finalize_kernel(float* __restrict__ loss_ptr /* may be null */) {
    __shared__ double rd[256];
    const int tid = threadIdx.x;
    double s = 0.0;
    for (int i = tid; i < B_ * D_; i += 256) s += (double)g_partial[i];
    rd[tid] = s;
    __syncthreads();
    for (int st = 128; st > 0; st >>= 1) {
        if (tid < st) rd[tid] += rd[tid + st];
        __syncthreads();
    }
    if (tid == 0 && loss_ptr) {
        float cl = (float)(rd[0] / (double)NQ_);
        loss_ptr[0] = __fadd_rn(cl, __fmul_rn(0.25f, cl));
    }
}

// ---------------------------------------------------------------------------
extern "C" void kernel_launch(void* const* d_in, const int* in_sizes, int n_in,
                              void* d_out, int out_size) {
    const float* z  = nullptr;
    const float* cb = nullptr;
    for (int i = 0; i < n_in; ++i) {
        if (in_sizes[i] == NQ_)        z  = (const float*)d_in[i];
        else if (in_sizes[i] == K_ * D_) cb = (const float*)d_in[i];
    }
    if (!z || !cb) return;

    float* out = (float*)d_out;
    float* loss_ptr = nullptr;
    float* q_ptr    = nullptr;
    float* i_ptr    = nullptr;

    if (out_size == 1 + NQ_ + N_) {          // (vq_loss, quantized, indices)
        loss_ptr = out; q_ptr = out + 1; i_ptr = out + 1 + NQ_;
    } else if (out_size == NQ_ + N_) {       // (quantized, indices)
        q_ptr = out; i_ptr = out + NQ_;
    } else if (out_size == NQ_ + N_ + 1) {
        loss_ptr = out; q_ptr = out + 1; i_ptr = out + 1 + NQ_;
    } else if (out_size == NQ_) {
        q_ptr = out;
    } else if (out_size == N_) {
        i_ptr = out;
    } else if (out_size == 1) {
        loss_ptr = out;
    } else if (out_size > 1 + NQ_ + N_) {    // unknown padding: assume tuple order
        loss_ptr = out; q_ptr = out + 1; i_ptr = out + 1 + NQ_;
    }

    static bool attr_done = false;
    const int smem_bytes = 131072 + 2048 + 65536;  // cb + norms + z tile
    if (!attr_done) {
        cudaFuncSetAttribute(argmin_kernel,
                             cudaFuncAttributeMaxDynamicSharedMemorySize,
                             smem_bytes);
        attr_done = true;
    }

    prep_kernel<<<2, 256>>>(cb);
    argmin_kernel<<<N_ / 256, 256, smem_bytes>>>(z, cb, i_ptr);
    gather_kernel<<<B_ * D_, 256>>>(z, cb, q_ptr);
    finalize_kernel<<<1, 256>>>(loss_ptr);
}

// round 2
// speedup vs baseline: 1.2169x; 1.2169x over previous
#include <cuda_runtime.h>

// Problem constants (fixed by the reference)
#define B_ 32
#define D_ 64
#define T_ 4096
#define K_ 512
#define N_ (B_ * T_)        // 131072 tokens
#define NQ_ (B_ * D_ * T_)  // 8388608 quantized elements

typedef unsigned long long u64;

// Scratch (device globals: no allocation allowed)
__device__ int          g_idx[N_];
__device__ float        g_cbnorm[K_];
__device__ float        g_partial[B_ * D_];   // 2048 per-block loss partials
__device__ unsigned int g_count;              // gather completion ticket

// ---------------------------------------------------------------------------
// Packed f32x2 helpers (SASS FFMA2 — 2 independent fp32 FMAs per instruction)
// ---------------------------------------------------------------------------
__device__ __forceinline__ u64 pack2(float lo, float hi) {
    u64 r;
    asm("mov.b64 %0, {%1, %2};" : "=l"(r) : "f"(lo), "f"(hi));
    return r;
}
__device__ __forceinline__ void unpack2(u64 v, float& lo, float& hi) {
    asm("mov.b64 {%0, %1}, %2;" : "=f"(lo), "=f"(hi) : "l"(v));
}
__device__ __forceinline__ void fma2(u64& acc, u64 a, u64 b) {
    asm("fma.rn.f32x2 %0, %1, %2, %0;" : "+l"(acc) : "l"(a), "l"(b));
}

// ---------------------------------------------------------------------------
// Kernel 0: codebook row norms  ||e_k||^2  (sequential fp32 fmaf, exact order
// preserved from the round-0 kernel that produced rel_err = 0)
// ---------------------------------------------------------------------------
__global__ void prep_kernel(const float* __restrict__ cb) {
    int k = blockIdx.x * blockDim.x + threadIdx.x;
    if (k < K_) {
        const float* r = cb + k * D_;
        float a = 0.0f;
#pragma unroll
        for (int i = 0; i < D_; ++i) a = fmaf(r[i], r[i], a);
        g_cbnorm[k] = a;
    }
}

// ---------------------------------------------------------------------------
// Kernel 1: argmin over K=512 codes for 256 tokens per block.
// dist_k = fl( fl(||z||^2 + ||e_k||^2) - fl(2 * (z . e_k)) )
// Dot uses 4 scalar chains (stride-4 subsets) realized as 2 packed f32x2
// accumulators whose lanes are EXACTLY the scalar chains -> bitwise identical
// to the round-0 kernel. Strict '<' keeps the FIRST index on ties.
// ---------------------------------------------------------------------------
__global__ __launch_bounds__(256, 1)
void argmin_kernel(const float* __restrict__ z,
                   const float* __restrict__ cb,
                   float* __restrict__ out_idx /* may be null */) {
    extern __shared__ char smraw[];
    float4* cb4 = reinterpret_cast<float4*>(smraw);                 // 512*16 float4 = 128KB
    float*  cn  = reinterpret_cast<float*>(smraw + 131072);         // 512 floats
    float*  zs  = reinterpret_cast<float*>(smraw + 131072 + 2048);  // 64*256 floats = 64KB

    const int tid = threadIdx.x;
    const int b   = blockIdx.x >> 4;          // 16 blocks per batch (4096/256)
    const int t0  = (blockIdx.x & 15) << 8;

    // Load codebook (coalesced, vectorized)
    const float4* cbg = reinterpret_cast<const float4*>(cb);
#pragma unroll 4
    for (int i = tid; i < K_ * 16; i += 256) cb4[i] = cbg[i];
    for (int i = tid; i < K_; i += 256) cn[i] = g_cbnorm[i];

    // Load z tile: zs[d][j] = z[b, d, t0 + j], coalesced over j
#pragma unroll 4
    for (int f = tid; f < D_ * 256; f += 256) {
        int d = f >> 8, j = f & 255;
        zs[f] = z[((b * D_ + d) << 12) + t0 + j];
    }
    __syncthreads();

    // Pull this thread's token into registers
    float zr[D_];
#pragma unroll
    for (int i = 0; i < D_; ++i) zr[i] = zs[i * 256 + tid];

    // ||z||^2 sequentially in fp32 (identical to round 0)
    float A = 0.0f;
#pragma unroll
    for (int i = 0; i < D_; ++i) A = fmaf(zr[i], zr[i], A);

    // Pack z into f32x2 operands: zp[2i] = (z[4i], z[4i+1]), zp[2i+1] = (z[4i+2], z[4i+3])
    u64 zp[32];
#pragma unroll
    for (int i = 0; i < 16; ++i) {
        zp[2 * i]     = pack2(zr[4 * i + 0], zr[4 * i + 1]);
        zp[2 * i + 1] = pack2(zr[4 * i + 2], zr[4 * i + 3]);
    }

    float bestd = 3.402823466e38f;
    int   bestk = 0;

    const ulonglong2* cb8 = reinterpret_cast<const ulonglong2*>(cb4);

#pragma unroll 2
    for (int k = 0; k < K_; ++k) {
        const ulonglong2* cp = cb8 + k * 16;
        u64 a01 = 0ull, a23 = 0ull;   // lanes = (s0,s1) and (s2,s3)
#pragma unroll
        for (int i = 0; i < 16; ++i) {
            ulonglong2 c = cp[i];     // c.x = (cb[4i], cb[4i+1]), c.y = (cb[4i+2], cb[4i+3])
            fma2(a01, zp[2 * i],     c.x);
            fma2(a23, zp[2 * i + 1], c.y);
        }
        float s0, s1, s2, s3;
        unpack2(a01, s0, s1);
        unpack2(a23, s2, s3);
        float dot  = __fadd_rn(__fadd_rn(s0, s1), __fadd_rn(s2, s3));
        float dist = __fadd_rn(__fadd_rn(A, cn[k]), -__fmul_rn(2.0f, dot));
        if (dist < bestd) { bestd = dist; bestk = k; }
    }

    const int n = b * T_ + t0 + tid;
    g_idx[n] = bestk;
    if (out_idx) out_idx[n] = (float)bestk;
}

// ---------------------------------------------------------------------------
// Kernel 2: gather quantized rows (straight-through arithmetic replicated:
// out = fl(z + fl(q - z))), deterministic per-block loss partials, and a
// fused last-block finalize (atomic ticket) producing vq_loss.
// One block per (b, d) row; coalesced over t.
// ---------------------------------------------------------------------------
__global__ __launch_bounds__(256)
void gather_kernel(const float* __restrict__ z,
                   const float* __restrict__ cb,
                   float* __restrict__ out_q /* may be null */,
                   float* __restrict__ loss_ptr /* may be null */) {
    __shared__ float  s_col[K_];
    __shared__ float  red[256];
    __shared__ bool   s_last;
    __shared__ double rd[256];

    const int tid = threadIdx.x;
    const int blk = blockIdx.x;     // 0 .. B_*D_-1
    const int b   = blk >> 6;
    const int d   = blk & 63;

    for (int i = tid; i < K_; i += 256) s_col[i] = cb[i * D_ + d];
    __syncthreads();

    const long rowoff = (long)(b * D_ + d) * T_;
    float acc = 0.0f;
#pragma unroll
    for (int j = 0; j < 16; ++j) {
        int t = j * 256 + tid;
        int idx = g_idx[b * T_ + t];
        float q  = s_col[idx];
        float zv = z[rowoff + t];
        float diff = __fsub_rn(q, zv);
        if (out_q) out_q[rowoff + t] = __fadd_rn(zv, diff);  // z + (q - z)
        acc = fmaf(diff, diff, acc);
    }

    red[tid] = acc;
    __syncthreads();
    for (int s = 128; s > 0; s >>= 1) {
        if (tid < s) red[tid] += red[tid + s];
        __syncthreads();
    }
    if (tid == 0) {
        g_partial[blk] = red[0];
        __threadfence();
        unsigned int ticket = atomicAdd(&g_count, 1u);
        s_last = (ticket == (unsigned)(B_ * D_ - 1));
    }
    __syncthreads();

    // Last block to finish performs the deterministic finalize.
    if (s_last) {
        double s = 0.0;
        for (int i = tid; i < B_ * D_; i += 256) s += (double)g_partial[i];
        rd[tid] = s;
        __syncthreads();
        for (int st = 128; st > 0; st >>= 1) {
            if (tid < st) rd[tid] += rd[tid + st];
            __syncthreads();
        }
        if (tid == 0) {
            if (loss_ptr) {
                float cl = (float)(rd[0] / (double)NQ_);
                loss_ptr[0] = __fadd_rn(cl, __fmul_rn(0.25f, cl));
            }
            g_count = 0;   // reset for next graph replay (deterministic)
        }
    }
}

// ---------------------------------------------------------------------------
extern "C" void kernel_launch(void* const* d_in, const int* in_sizes, int n_in,
                              void* d_out, int out_size) {
    const float* z  = nullptr;
    const float* cb = nullptr;
    for (int i = 0; i < n_in; ++i) {
        if (in_sizes[i] == NQ_)          z  = (const float*)d_in[i];
        else if (in_sizes[i] == K_ * D_) cb = (const float*)d_in[i];
    }
    if (!z || !cb) return;

    float* out = (float*)d_out;
    float* loss_ptr = nullptr;
    float* q_ptr    = nullptr;
    float* i_ptr    = nullptr;

    if (out_size == 1 + NQ_ + N_) {          // (vq_loss, quantized, indices)
        loss_ptr = out; q_ptr = out + 1; i_ptr = out + 1 + NQ_;
    } else if (out_size == NQ_ + N_) {       // (quantized, indices)
        q_ptr = out; i_ptr = out + NQ_;
    } else if (out_size == NQ_) {
        q_ptr = out;
    } else if (out_size == N_) {
        i_ptr = out;
    } else if (out_size == 1) {
        loss_ptr = out;
    } else if (out_size > 1 + NQ_ + N_) {    // unknown padding: assume tuple order
        loss_ptr = out; q_ptr = out + 1; i_ptr = out + 1 + NQ_;
    }

    static bool attr_done = false;
    const int smem_bytes = 131072 + 2048 + 65536;  // cb + norms + z tile
    if (!attr_done) {
        cudaFuncSetAttribute(argmin_kernel,
                             cudaFuncAttributeMaxDynamicSharedMemorySize,
                             smem_bytes);
        attr_done = true;
    }

    prep_kernel<<<2, 256>>>(cb);
    argmin_kernel<<<N_ / 256, 256, smem_bytes>>>(z, cb, i_ptr);
    gather_kernel<<<B_ * D_, 256>>>(z, cb, q_ptr, loss_ptr);
}